// round 6
// baseline (speedup 1.0000x reference)
#include <cuda_runtime.h>
#include <math.h>
#include <cstdint>

#define NN 50000
#define DH 128
#define EE 600000

// ---------------- scratch ------------------------------------------------------
__device__ float g_x[NN * DH];       // x1 (head out), later y2
__device__ float g_y[NN * DH];       // y1 (gather out), later h2
__device__ float g_h[NN * DH];       // h1
__device__ float g_z[NN];
__device__ float g_stats[2];
__device__ int   g_deg[NN];
__device__ int   g_rowstart[NN + 1];
__device__ int   g_cursor[NN];
__device__ int   g_adj[EE];
__device__ float g_WF[DH * DH];      // lin_W1 @ gin_W2
__device__ float g_bf[DH];           // lin_b1 @ gin_W2
__device__ float g_v2[DH];           // lin_W2 @ tail_W
__device__ float g_zb[1];            // lin_b2 . tail_W + tail_b

// ---------------- f32x2 helpers ------------------------------------------------
__device__ __forceinline__ unsigned long long packdup(float x) {
    unsigned long long r;
    uint32_t u = __float_as_uint(x);
    asm("mov.b64 %0, {%1, %2};" : "=l"(r) : "r"(u), "r"(u));
    return r;
}
__device__ __forceinline__ void fma2(unsigned long long& d, unsigned long long a,
                                     unsigned long long b) {
    asm("fma.rn.f32x2 %0, %1, %2, %0;" : "+l"(d) : "l"(a), "l"(b));
}
__device__ __forceinline__ float2 unpk(unsigned long long v) {
    uint32_t lo, hi;
    asm("mov.b64 {%0, %1}, %2;" : "=r"(lo), "=r"(hi) : "l"(v));
    return make_float2(__uint_as_float(lo), __uint_as_float(hi));
}

// ---------------- GEMM: out[M,128] = relu(A[M,K] @ W[K,128] + bias) ------------
// MODE 0: bias[col].  MODE 1: bias[col] = b2[col] + (1+deg_row)*bf[col].
// BM=64, BN=128, BK=32, 256 threads, 8x4 microtile via f32x2 (row-paired).
template <int MODE>
__global__ void __launch_bounds__(256, 3)
gemm_k(const float* __restrict__ A, const float* __restrict__ W,
       const float* __restrict__ bias, const float* __restrict__ bf,
       const int* __restrict__ rowstart,
       float* __restrict__ out, int M, int K)
{
    constexpr int BM = 64;
    constexpr int BK = 32;

    __shared__ float As[BK][BM + 4];   // K-major; row stride 272B (8B-aligned)
    __shared__ float Bs[BK][128];

    const int tid  = threadIdx.x;
    const int tcol = tid & 31;         // cols 4*tcol .. 4*tcol+3
    const int trow = tid >> 5;         // rows 8*trow .. 8*trow+7
    const int rowBase = blockIdx.x * BM;

    unsigned long long acc[4][4];      // [row-pair][col]; pair = rows (2rp,2rp+1)
#pragma unroll
    for (int i = 0; i < 4; i++)
#pragma unroll
        for (int j = 0; j < 4; j++) acc[i][j] = 0ull;

    for (int k0 = 0; k0 < K; k0 += BK) {
        // A tile (64x32) -> transpose into As[k][row]
#pragma unroll
        for (int t = 0; t < 2; t++) {
            int i  = tid + t * 256;
            int r  = i >> 3;
            int c4 = i & 7;
            int row = rowBase + r;
            float4 v = make_float4(0.f, 0.f, 0.f, 0.f);
            if (row < M)
                v = *(const float4*)&A[(size_t)row * K + k0 + c4 * 4];
            As[c4 * 4 + 0][r] = v.x;
            As[c4 * 4 + 1][r] = v.y;
            As[c4 * 4 + 2][r] = v.z;
            As[c4 * 4 + 3][r] = v.w;
        }
        // B tile (32x128)
#pragma unroll
        for (int t = 0; t < 4; t++) {
            int i  = tid + t * 256;
            int r  = i >> 5;
            int c4 = i & 31;
            *(float4*)&Bs[r][c4 * 4] =
                *(const float4*)&W[(size_t)(k0 + r) * 128 + c4 * 4];
        }
        __syncthreads();

#pragma unroll
        for (int kk = 0; kk < BK; kk++) {
            unsigned long long ap[4];
#pragma unroll
            for (int rp = 0; rp < 4; rp++)
                ap[rp] = *(const unsigned long long*)&As[kk][trow * 8 + rp * 2];
            float4 b = *(const float4*)&Bs[kk][tcol * 4];
            unsigned long long bd[4];
            bd[0] = packdup(b.x); bd[1] = packdup(b.y);
            bd[2] = packdup(b.z); bd[3] = packdup(b.w);
#pragma unroll
            for (int rp = 0; rp < 4; rp++)
#pragma unroll
                for (int j = 0; j < 4; j++)
                    fma2(acc[rp][j], ap[rp], bd[j]);
        }
        __syncthreads();
    }

    // ---- epilogue
    float bbase[4];
#pragma unroll
    for (int j = 0; j < 4; j++) bbase[j] = bias[tcol * 4 + j];
    float bfv[4];
    if (MODE == 1) {
#pragma unroll
        for (int j = 0; j < 4; j++) bfv[j] = bf[tcol * 4 + j];
    }

#pragma unroll
    for (int rp = 0; rp < 4; rp++) {
        float2 c0 = unpk(acc[rp][0]);
        float2 c1 = unpk(acc[rp][1]);
        float2 c2 = unpk(acc[rp][2]);
        float2 c3 = unpk(acc[rp][3]);
        int r0 = rowBase + trow * 8 + rp * 2;
#pragma unroll
        for (int half = 0; half < 2; half++) {
            int row = r0 + half;
            if (row < M) {
                float4 o;
                o.x = half ? c0.y : c0.x;
                o.y = half ? c1.y : c1.x;
                o.z = half ? c2.y : c2.x;
                o.w = half ? c3.y : c3.x;
                if (MODE == 1) {
                    float s = 1.f + (float)(__ldg(&rowstart[row + 1]) - __ldg(&rowstart[row]));
                    o.x += bbase[0] + s * bfv[0];
                    o.y += bbase[1] + s * bfv[1];
                    o.z += bbase[2] + s * bfv[2];
                    o.w += bbase[3] + s * bfv[3];
                } else {
                    o.x += bbase[0]; o.y += bbase[1];
                    o.z += bbase[2]; o.w += bbase[3];
                }
                o.x = fmaxf(o.x, 0.f); o.y = fmaxf(o.y, 0.f);
                o.z = fmaxf(o.z, 0.f); o.w = fmaxf(o.w, 0.f);
                *(float4*)&out[(size_t)row * 128 + tcol * 4] = o;
            }
        }
    }
}

// ---------------- weight folding ----------------------------------------------
// WF[i][j] = sum_k L1[i][k] * G2[k][j]
__global__ void fold_W_k(const float* __restrict__ L1, const float* __restrict__ G2,
                         float* __restrict__ WF)
{
    int idx = blockIdx.x * blockDim.x + threadIdx.x;   // 16384
    int i = idx >> 7, j = idx & 127;
    float s = 0.f;
    for (int k = 0; k < 128; k++)
        s = fmaf(L1[i * 128 + k], G2[k * 128 + j], s);
    WF[idx] = s;
}
// bf[j] = sum_i b_l1[i] * G2[i][j]
__global__ void fold_b_k(const float* __restrict__ bl1, const float* __restrict__ G2,
                         float* __restrict__ bf)
{
    int j = threadIdx.x;
    float s = 0.f;
    for (int i = 0; i < 128; i++)
        s = fmaf(bl1[i], G2[i * 128 + j], s);
    bf[j] = s;
}
// v2[i] = sum_k L2[i][k]*T[k];  zb = sum_k bl2[k]*T[k] + bt
__global__ void fold_t_k(const float* __restrict__ L2, const float* __restrict__ T,
                         const float* __restrict__ bl2, const float* __restrict__ bt,
                         float* __restrict__ v2, float* __restrict__ zb)
{
    int i = threadIdx.x;
    float s = 0.f;
    for (int k = 0; k < 128; k++)
        s = fmaf(L2[i * 128 + k], T[k], s);
    v2[i] = s;
    if (i == 0) {
        float z = bt[0];
        for (int k = 0; k < 128; k++) z = fmaf(bl2[k], T[k], z);
        zb[0] = z;
    }
}

// ---------------- CSR build ----------------------------------------------------
__global__ void zero_deg_k(int* __restrict__ deg)
{
    int i = blockIdx.x * blockDim.x + threadIdx.x;
    if (i < NN) deg[i] = 0;
}
__global__ void degree_k(const int* __restrict__ ei, int* __restrict__ deg)
{
    int e = blockIdx.x * blockDim.x + threadIdx.x;
    if (e < EE) atomicAdd(&deg[ei[EE + e]], 1);
}
__global__ void scan_k(const int* __restrict__ deg, int* __restrict__ rowstart,
                       int* __restrict__ cursor)
{
    __shared__ int sh[1024];
    const int tid = threadIdx.x;
    const int CH  = (NN + 1023) / 1024;
    const int base = tid * CH;

    int s = 0;
    for (int i = 0; i < CH; i++) {
        int idx = base + i;
        if (idx < NN) s += deg[idx];
    }
    sh[tid] = s;
    __syncthreads();
    for (int o = 1; o < 1024; o <<= 1) {
        int v = (tid >= o) ? sh[tid - o] : 0;
        __syncthreads();
        sh[tid] += v;
        __syncthreads();
    }
    int run = sh[tid] - s;
    for (int i = 0; i < CH; i++) {
        int idx = base + i;
        if (idx < NN) {
            rowstart[idx] = run;
            cursor[idx]   = run;
            run += deg[idx];
        }
    }
    if (tid == 1023) rowstart[NN] = sh[1023];
}
__global__ void fill_k(const int* __restrict__ ei, int* __restrict__ cursor,
                       int* __restrict__ adj)
{
    int e = blockIdx.x * blockDim.x + threadIdx.x;
    if (e < EE) {
        int s = ei[e];
        int d = ei[EE + e];
        int p = atomicAdd(&cursor[d], 1);
        adj[p] = s;
    }
}

// ---------------- gather: y[n] = x[n] + sum_{s in N(n)} x[s] -------------------
__global__ void gather_k(const float* __restrict__ x,
                         const int* __restrict__ rowstart,
                         const int* __restrict__ adj,
                         float* __restrict__ y)
{
    int idx = blockIdx.x * blockDim.x + threadIdx.x;
    int n = idx >> 5;
    if (n >= NN) return;
    int l = idx & 31;

    float4 acc = *(const float4*)&x[(size_t)n * 128 + l * 4];
    int start = __ldg(&rowstart[n]);
    int end   = __ldg(&rowstart[n + 1]);
    for (int j = start; j < end; j++) {
        int s = __ldg(&adj[j]);
        float4 v = *(const float4*)&x[(size_t)s * 128 + l * 4];
        acc.x += v.x; acc.y += v.y; acc.z += v.z; acc.w += v.w;
    }
    *(float4*)&y[(size_t)n * 128 + l * 4] = acc;
}

// ---------------- tail dot: z = x . v2 + zb ------------------------------------
__global__ void tail_k(const float* __restrict__ x, const float* __restrict__ W,
                       const float* __restrict__ zb, float* __restrict__ z)
{
    int idx = blockIdx.x * blockDim.x + threadIdx.x;
    int row = idx >> 5;
    if (row >= NN) return;
    int l = idx & 31;
    float4 xv = *(const float4*)&x[(size_t)row * 128 + l * 4];
    float4 wv = *(const float4*)&W[l * 4];
    float s = xv.x * wv.x + xv.y * wv.y + xv.z * wv.z + xv.w * wv.w;
#pragma unroll
    for (int o = 16; o; o >>= 1) s += __shfl_xor_sync(0xFFFFFFFFu, s, o);
    if (l == 0) z[row] = s + zb[0];
}

// ---------------- BN -----------------------------------------------------------
__global__ void stats_k(const float* __restrict__ z, float* __restrict__ stats)
{
    __shared__ float sh[1024];
    int tid = threadIdx.x;

    float s = 0.f;
    for (int i = tid; i < NN; i += 1024) s += z[i];
    sh[tid] = s;
    __syncthreads();
    for (int o = 512; o > 0; o >>= 1) {
        if (tid < o) sh[tid] += sh[tid + o];
        __syncthreads();
    }
    float mu = sh[0] / (float)NN;
    __syncthreads();

    float v = 0.f;
    for (int i = tid; i < NN; i += 1024) {
        float d = z[i] - mu;
        v += d * d;
    }
    sh[tid] = v;
    __syncthreads();
    for (int o = 512; o > 0; o >>= 1) {
        if (tid < o) sh[tid] += sh[tid + o];
        __syncthreads();
    }
    if (tid == 0) {
        stats[0] = mu;
        stats[1] = rsqrtf(sh[0] / (float)NN + 1e-5f);
    }
}
__global__ void bn_k(const float* __restrict__ z, const float* __restrict__ stats,
                     const float* __restrict__ gamma, const float* __restrict__ beta,
                     float* __restrict__ out)
{
    int i = blockIdx.x * blockDim.x + threadIdx.x;
    if (i < NN) {
        out[i] = (z[i] - stats[0]) * stats[1] * gamma[0] + beta[0];
    }
}

// ---------------- launcher ------------------------------------------------------
extern "C" void kernel_launch(void* const* d_in, const int* in_sizes, int n_in,
                              void* d_out, int out_size)
{
    const float* feature = (const float*)d_in[0];
    const int*   ei      = (const int*)d_in[1];
    const float* head_W  = (const float*)d_in[2];
    const float* head_b  = (const float*)d_in[3];
    const float* gin_W1  = (const float*)d_in[4];
    const float* gin_b1  = (const float*)d_in[5];
    const float* lin_W1  = (const float*)d_in[6];
    const float* lin_b1  = (const float*)d_in[7];
    const float* gin_W2  = (const float*)d_in[8];
    const float* gin_b2  = (const float*)d_in[9];
    const float* lin_W2  = (const float*)d_in[10];
    const float* lin_b2  = (const float*)d_in[11];
    const float* tail_W  = (const float*)d_in[12];
    const float* tail_b  = (const float*)d_in[13];
    const float* bn_g    = (const float*)d_in[14];
    const float* bn_b    = (const float*)d_in[15];
    float* out = (float*)d_out;

    float *xp, *yp, *hp, *zp, *stp, *wfp, *bfp, *v2p, *zbp;
    int *degp, *rsp, *curp, *adjp;
    cudaGetSymbolAddress((void**)&xp,   g_x);
    cudaGetSymbolAddress((void**)&yp,   g_y);
    cudaGetSymbolAddress((void**)&hp,   g_h);
    cudaGetSymbolAddress((void**)&zp,   g_z);
    cudaGetSymbolAddress((void**)&stp,  g_stats);
    cudaGetSymbolAddress((void**)&degp, g_deg);
    cudaGetSymbolAddress((void**)&rsp,  g_rowstart);
    cudaGetSymbolAddress((void**)&curp, g_cursor);
    cudaGetSymbolAddress((void**)&adjp, g_adj);
    cudaGetSymbolAddress((void**)&wfp,  g_WF);
    cudaGetSymbolAddress((void**)&bfp,  g_bf);
    cudaGetSymbolAddress((void**)&v2p,  g_v2);
    cudaGetSymbolAddress((void**)&zbp,  g_zb);

    const int gemmGrid = (NN + 63) / 64;
    const int edgeGrid = (EE + 255) / 256;
    const int nodeGrid = (NN + 255) / 256;
    const int warpGrid = (NN * 32 + 255) / 256;

    // ---- weight folds (tiny, independent) ----
    fold_W_k<<<64, 256>>>(lin_W1, gin_W2, wfp);
    fold_b_k<<<1, 128>>>(lin_b1, gin_W2, bfp);
    fold_t_k<<<1, 128>>>(lin_W2, tail_W, lin_b2, tail_b, v2p, zbp);

    // ---- CSR build ----
    zero_deg_k<<<nodeGrid, 256>>>(degp);
    degree_k<<<edgeGrid, 256>>>(ei, degp);
    scan_k<<<1, 1024>>>(degp, rsp, curp);
    fill_k<<<edgeGrid, 256>>>(ei, curp, adjp);

    // head: x1 = relu(feature @ head_W + head_b)
    gemm_k<0><<<gemmGrid, 256>>>(feature, head_W, head_b, nullptr, nullptr, xp, NN, 512);

    // GIN layer 1 MLP first half: h1 = relu((x1 + agg(x1)) @ gin_W1 + gin_b1)
    gather_k<<<warpGrid, 256>>>(xp, rsp, adjp, yp);
    gemm_k<0><<<gemmGrid, 256>>>(yp, gin_W1, gin_b1, nullptr, nullptr, hp, NN, 128);

    // Layer 2 with lin_W1 folded: y2 = h1 + agg(h1);
    // h2 = relu(y2 @ (L1 G2) + gin_b2 + (1+deg)*(b_l1 G2))
    gather_k<<<warpGrid, 256>>>(hp, rsp, adjp, xp);
    gemm_k<1><<<gemmGrid, 256>>>(xp, wfp, gin_b2, bfp, rsp, yp, NN, 128);

    // tail (lin_W2/tail folded): z = h2 . v2 + zb, then BN
    tail_k<<<warpGrid, 256>>>(yp, v2p, zbp, zp);
    stats_k<<<1, 1024>>>(zp, stp);
    bn_k<<<nodeGrid, 256>>>(zp, stp, bn_g, bn_b, out);
}

// round 9
// speedup vs baseline: 2.1884x; 2.1884x over previous
#include <cuda_runtime.h>
#include <cuda_bf16.h>
#include <math.h>
#include <cstdint>

#define NN 50000
#define DH 128
#define EE 600000

// ---------------- scratch ------------------------------------------------------
__device__ float g_x[NN * DH];
__device__ float g_y[NN * DH];
__device__ float g_h[NN * DH];
__device__ float g_z[NN];
__device__ float g_stats[2];
__device__ int   g_deg[NN];
__device__ int   g_rowstart[NN + 1];
__device__ int   g_cursor[NN];
__device__ int   g_adj[EE];
__device__ float g_WF[DH * DH];      // lin_W1 @ gin_W2
__device__ float g_bf[DH];           // lin_b1 @ gin_W2
__device__ float g_v2[DH];           // lin_W2 @ tail_W
__device__ float g_zb[1];            // lin_b2 . tail_W + tail_b
// Pre-converted weights: 6 chunks (head:0..3, gin_W1:4, WF:5), swizzled smem image.
// Each chunk image: 128 k-rows x 256B = 32KB = 16384 bf16.
__device__ uint16_t g_Whi[6 * 16384];
__device__ uint16_t g_Wlo[6 * 16384];

// ---------------- helpers ------------------------------------------------------
__device__ __forceinline__ uint32_t smem_u32(const void* p) {
    uint32_t a;
    asm("{ .reg .u64 t; cvta.to.shared.u64 t, %1; cvt.u32.u64 %0, t; }" : "=r"(a) : "l"(p));
    return a;
}
__device__ __forceinline__ void ldsm_x4(uint32_t* r, uint32_t addr) {
    asm volatile("ldmatrix.sync.aligned.m8n8.x4.shared.b16 {%0,%1,%2,%3}, [%4];"
                 : "=r"(r[0]), "=r"(r[1]), "=r"(r[2]), "=r"(r[3]) : "r"(addr));
}
__device__ __forceinline__ void ldsm_x4_t(uint32_t* r, uint32_t addr) {
    asm volatile("ldmatrix.sync.aligned.m8n8.x4.trans.shared.b16 {%0,%1,%2,%3}, [%4];"
                 : "=r"(r[0]), "=r"(r[1]), "=r"(r[2]), "=r"(r[3]) : "r"(addr));
}
__device__ __forceinline__ void mma16816(float* d, const uint32_t* a, const uint32_t* b) {
    asm volatile(
        "mma.sync.aligned.m16n8k16.row.col.f32.bf16.bf16.f32 "
        "{%0,%1,%2,%3}, {%4,%5,%6,%7}, {%8,%9}, {%0,%1,%2,%3};"
        : "+f"(d[0]), "+f"(d[1]), "+f"(d[2]), "+f"(d[3])
        : "r"(a[0]), "r"(a[1]), "r"(a[2]), "r"(a[3]), "r"(b[0]), "r"(b[1]));
}
__device__ __forceinline__ uint32_t pack2(__nv_bfloat16 x, __nv_bfloat16 y) {
    __nv_bfloat162 t(x, y);
    return *(uint32_t*)&t;
}
// swizzled byte offset inside a 256B-row tile (row-major, 2B elems)
__device__ __forceinline__ uint32_t sw_off(int row, int col) {
    return (uint32_t)row * 256u + (((uint32_t)col * 2u) ^ (((uint32_t)row & 7u) << 4));
}

static constexpr int OA_HI = 0;
static constexpr int OA_LO = 16384;
static constexpr int OB_HI = 32768;
static constexpr int OB_LO = 65536;
static constexpr int SMEM_GEMM = 98304;

// ---------------- weight pre-conversion ----------------------------------------
// W: [K x 128] fp32 -> per-chunk swizzled bf16 hi/lo images at chunkBase.
__global__ void conv_w_k(const float* __restrict__ W, uint16_t* __restrict__ Whi,
                         uint16_t* __restrict__ Wlo, int K, int chunkBase)
{
    int idx = blockIdx.x * blockDim.x + threadIdx.x;   // K*128 elems
    if (idx >= K * 128) return;
    int k = idx >> 7;
    int n = idx & 127;
    float v = W[idx];
    __nv_bfloat16 h = __float2bfloat16(v);
    __nv_bfloat16 l = __float2bfloat16(v - __bfloat162float(h));
    int c  = k >> 7;
    int kk = k & 127;
    uint32_t o = ((uint32_t)(chunkBase + c) * 32768u + sw_off(kk, n)) >> 1;
    Whi[o] = *(uint16_t*)&h;
    Wlo[o] = *(uint16_t*)&l;
}

// ---------------- HMMA GEMM: out[M,128] = relu?(A[M,K]@W + bias) ---------------
// B pre-converted (swizzled global images). 3-split: Ah*Bh + Ah*Bl + Al*Bh.
// MODE 0: bias[col]. MODE 1: bias[col] + (1+deg_row)*bf[col].
template <bool RELU, int MODE>
__global__ void __launch_bounds__(256, 2)
mma_gemm(const float* __restrict__ A,
         const uint4* __restrict__ Whi, const uint4* __restrict__ Wlo,
         const float* __restrict__ bias, const float* __restrict__ bf,
         const int* __restrict__ rowstart,
         float* __restrict__ out, int M, int K, int chunkBase)
{
    extern __shared__ char smem[];
    const uint32_t sb = smem_u32(smem);
    const int tid  = threadIdx.x;
    const int wid  = tid >> 5;
    const int lane = tid & 31;
    const int wm = wid & 1;
    const int wn = wid >> 1;
    const int rowBase = blockIdx.x * 64;

    float acc[2][4][4];
#pragma unroll
    for (int i = 0; i < 2; i++)
#pragma unroll
        for (int j = 0; j < 4; j++)
#pragma unroll
            for (int q = 0; q < 4; q++) acc[i][j][q] = 0.f;

    const int grp = lane >> 3;
    const int li  = lane & 7;

    const int nchunk = K >> 7;
    for (int c = 0; c < nchunk; c++) {
        __syncthreads();
        // ---- fill A: 64 rows x 128 k, fp32 -> bf16 hi/lo, swizzled
#pragma unroll
        for (int t = 0; t < 8; t++) {
            int slot = tid + t * 256;
            int r  = slot >> 5;
            int k4 = (slot & 31) * 4;
            int grow = rowBase + r;
            float4 v = make_float4(0.f, 0.f, 0.f, 0.f);
            if (grow < M)
                v = *(const float4*)&A[(size_t)grow * K + c * 128 + k4];
            __nv_bfloat16 h0 = __float2bfloat16(v.x), h1 = __float2bfloat16(v.y);
            __nv_bfloat16 h2 = __float2bfloat16(v.z), h3 = __float2bfloat16(v.w);
            float l0 = v.x - __bfloat162float(h0), l1 = v.y - __bfloat162float(h1);
            float l2 = v.z - __bfloat162float(h2), l3 = v.w - __bfloat162float(h3);
            uint32_t o = sw_off(r, k4);
            *(uint32_t*)(smem + OA_HI + o)     = pack2(h0, h1);
            *(uint32_t*)(smem + OA_HI + o + 4) = pack2(h2, h3);
            *(uint32_t*)(smem + OA_LO + o)     = pack2(__float2bfloat16(l0), __float2bfloat16(l1));
            *(uint32_t*)(smem + OA_LO + o + 4) = pack2(__float2bfloat16(l2), __float2bfloat16(l3));
        }
        // ---- fill B: plain uint4 copy of pre-swizzled bf16 images (2048 each)
        const uint4* srcHi = Whi + (size_t)(chunkBase + c) * 2048;
        const uint4* srcLo = Wlo + (size_t)(chunkBase + c) * 2048;
#pragma unroll
        for (int t = 0; t < 8; t++) {
            int slot = tid + t * 256;
            ((uint4*)(smem + OB_HI))[slot] = __ldg(&srcHi[slot]);
            ((uint4*)(smem + OB_LO))[slot] = __ldg(&srcLo[slot]);
        }
        __syncthreads();

        // ---- 8 k-steps of 16
#pragma unroll
        for (int ks = 0; ks < 8; ks++) {
            int k0 = ks * 16;
            uint32_t ah[2][4], al[2][4];
#pragma unroll
            for (int mt = 0; mt < 2; mt++) {
                int r = wm * 32 + mt * 16 + li + (grp & 1) * 8;
                int kk = k0 + (grp >> 1) * 8;
                uint32_t addr = sb + OA_HI + sw_off(r, kk);
                ldsm_x4(ah[mt], addr);
                ldsm_x4(al[mt], addr + (OA_LO - OA_HI));
            }
            uint32_t bh[4][2], bl[4][2];
#pragma unroll
            for (int ntp = 0; ntp < 2; ntp++) {
                int kk = k0 + li + (grp & 1) * 8;
                int n  = wn * 32 + ntp * 16 + (grp >> 1) * 8;
                uint32_t addr = sb + OB_HI + sw_off(kk, n);
                uint32_t r4[4];
                ldsm_x4_t(r4, addr);
                bh[ntp * 2][0] = r4[0]; bh[ntp * 2][1] = r4[1];
                bh[ntp * 2 + 1][0] = r4[2]; bh[ntp * 2 + 1][1] = r4[3];
                ldsm_x4_t(r4, addr + (OB_LO - OB_HI));
                bl[ntp * 2][0] = r4[0]; bl[ntp * 2][1] = r4[1];
                bl[ntp * 2 + 1][0] = r4[2]; bl[ntp * 2 + 1][1] = r4[3];
            }
#pragma unroll
            for (int mt = 0; mt < 2; mt++)
#pragma unroll
                for (int nt = 0; nt < 4; nt++)
                    mma16816(acc[mt][nt], ah[mt], bh[nt]);
#pragma unroll
            for (int mt = 0; mt < 2; mt++)
#pragma unroll
                for (int nt = 0; nt < 4; nt++)
                    mma16816(acc[mt][nt], ah[mt], bl[nt]);
#pragma unroll
            for (int mt = 0; mt < 2; mt++)
#pragma unroll
                for (int nt = 0; nt < 4; nt++)
                    mma16816(acc[mt][nt], al[mt], bh[nt]);
        }
    }

    // ---- epilogue
#pragma unroll
    for (int mt = 0; mt < 2; mt++) {
#pragma unroll
        for (int nt = 0; nt < 4; nt++) {
            int r0 = rowBase + wm * 32 + mt * 16 + (lane >> 2);
            int cc = wn * 32 + nt * 8 + (lane & 3) * 2;
            float b0 = __ldg(&bias[cc]);
            float b1 = __ldg(&bias[cc + 1]);
            float f0 = 0.f, f1 = 0.f;
            if (MODE == 1) { f0 = __ldg(&bf[cc]); f1 = __ldg(&bf[cc + 1]); }
#pragma unroll
            for (int half = 0; half < 2; half++) {
                int row = r0 + half * 8;
                if (row < M) {
                    float v0 = acc[mt][nt][half * 2 + 0];
                    float v1 = acc[mt][nt][half * 2 + 1];
                    if (MODE == 1) {
                        float s = 1.f + (float)(__ldg(&rowstart[row + 1]) - __ldg(&rowstart[row]));
                        v0 += b0 + s * f0;
                        v1 += b1 + s * f1;
                    } else {
                        v0 += b0; v1 += b1;
                    }
                    if (RELU) { v0 = fmaxf(v0, 0.f); v1 = fmaxf(v1, 0.f); }
                    *(float2*)&out[(size_t)row * 128 + cc] = make_float2(v0, v1);
                }
            }
        }
    }
}

// ---------------- weight folding ----------------------------------------------
__global__ void fold_W_k(const float* __restrict__ L1, const float* __restrict__ G2,
                         float* __restrict__ WF)
{
    int idx = blockIdx.x * blockDim.x + threadIdx.x;
    int i = idx >> 7, j = idx & 127;
    float s = 0.f;
    for (int k = 0; k < 128; k++)
        s = fmaf(L1[i * 128 + k], G2[k * 128 + j], s);
    WF[idx] = s;
}
__global__ void fold_b_k(const float* __restrict__ bl1, const float* __restrict__ G2,
                         float* __restrict__ bf)
{
    int j = threadIdx.x;
    float s = 0.f;
    for (int i = 0; i < 128; i++)
        s = fmaf(bl1[i], G2[i * 128 + j], s);
    bf[j] = s;
}
__global__ void fold_t_k(const float* __restrict__ L2, const float* __restrict__ T,
                         const float* __restrict__ bl2, const float* __restrict__ bt,
                         float* __restrict__ v2, float* __restrict__ zb)
{
    int i = threadIdx.x;
    float s = 0.f;
    for (int k = 0; k < 128; k++)
        s = fmaf(L2[i * 128 + k], T[k], s);
    v2[i] = s;
    if (i == 0) {
        float z = bt[0];
        for (int k = 0; k < 128; k++) z = fmaf(bl2[k], T[k], z);
        zb[0] = z;
    }
}

// ---------------- CSR build ----------------------------------------------------
__global__ void zero_deg_k(int* __restrict__ deg)
{
    int i = blockIdx.x * blockDim.x + threadIdx.x;
    if (i < NN) deg[i] = 0;
}
__global__ void degree_k(const int* __restrict__ ei, int* __restrict__ deg)
{
    int e = blockIdx.x * blockDim.x + threadIdx.x;
    if (e < EE) atomicAdd(&deg[ei[EE + e]], 1);
}
__global__ void scan_k(const int* __restrict__ deg, int* __restrict__ rowstart,
                       int* __restrict__ cursor)
{
    __shared__ int sh[1024];
    const int tid = threadIdx.x;
    const int CH  = (NN + 1023) / 1024;
    const int base = tid * CH;

    int s = 0;
    for (int i = 0; i < CH; i++) {
        int idx = base + i;
        if (idx < NN) s += deg[idx];
    }
    sh[tid] = s;
    __syncthreads();
    for (int o = 1; o < 1024; o <<= 1) {
        int v = (tid >= o) ? sh[tid - o] : 0;
        __syncthreads();
        sh[tid] += v;
        __syncthreads();
    }
    int run = sh[tid] - s;
    for (int i = 0; i < CH; i++) {
        int idx = base + i;
        if (idx < NN) {
            rowstart[idx] = run;
            cursor[idx]   = run;
            run += deg[idx];
        }
    }
    if (tid == 1023) rowstart[NN] = sh[1023];
}
__global__ void fill_k(const int* __restrict__ ei, int* __restrict__ cursor,
                       int* __restrict__ adj)
{
    int e = blockIdx.x * blockDim.x + threadIdx.x;
    if (e < EE) {
        int s = ei[e];
        int d = ei[EE + e];
        int p = atomicAdd(&cursor[d], 1);
        adj[p] = s;
    }
}

// ---------------- gather: y[n] = x[n] + sum_{s in N(n)} x[s] -------------------
__global__ void gather_k(const float* __restrict__ x,
                         const int* __restrict__ rowstart,
                         const int* __restrict__ adj,
                         float* __restrict__ y)
{
    int idx = blockIdx.x * blockDim.x + threadIdx.x;
    int n = idx >> 5;
    if (n >= NN) return;
    int l = idx & 31;

    float4 acc = *(const float4*)&x[(size_t)n * 128 + l * 4];
    int start = __ldg(&rowstart[n]);
    int end   = __ldg(&rowstart[n + 1]);
    for (int j = start; j < end; j++) {
        int s = __ldg(&adj[j]);
        float4 v = *(const float4*)&x[(size_t)s * 128 + l * 4];
        acc.x += v.x; acc.y += v.y; acc.z += v.z; acc.w += v.w;
    }
    *(float4*)&y[(size_t)n * 128 + l * 4] = acc;
}

// ---------------- tail dot: z = x . v2 + zb ------------------------------------
__global__ void tail_k(const float* __restrict__ x, const float* __restrict__ W,
                       const float* __restrict__ zb, float* __restrict__ z)
{
    int idx = blockIdx.x * blockDim.x + threadIdx.x;
    int row = idx >> 5;
    if (row >= NN) return;
    int l = idx & 31;
    float4 xv = *(const float4*)&x[(size_t)row * 128 + l * 4];
    float4 wv = *(const float4*)&W[l * 4];
    float s = xv.x * wv.x + xv.y * wv.y + xv.z * wv.z + xv.w * wv.w;
#pragma unroll
    for (int o = 16; o; o >>= 1) s += __shfl_xor_sync(0xFFFFFFFFu, s, o);
    if (l == 0) z[row] = s + zb[0];
}

// ---------------- BN -----------------------------------------------------------
__global__ void stats_k(const float* __restrict__ z, float* __restrict__ stats)
{
    __shared__ float sh[1024];
    int tid = threadIdx.x;

    float s = 0.f;
    for (int i = tid; i < NN; i += 1024) s += z[i];
    sh[tid] = s;
    __syncthreads();
    for (int o = 512; o > 0; o >>= 1) {
        if (tid < o) sh[tid] += sh[tid + o];
        __syncthreads();
    }
    float mu = sh[0] / (float)NN;
    __syncthreads();

    float v = 0.f;
    for (int i = tid; i < NN; i += 1024) {
        float d = z[i] - mu;
        v += d * d;
    }
    sh[tid] = v;
    __syncthreads();
    for (int o = 512; o > 0; o >>= 1) {
        if (tid < o) sh[tid] += sh[tid + o];
        __syncthreads();
    }
    if (tid == 0) {
        stats[0] = mu;
        stats[1] = rsqrtf(sh[0] / (float)NN + 1e-5f);
    }
}
__global__ void bn_k(const float* __restrict__ z, const float* __restrict__ stats,
                     const float* __restrict__ gamma, const float* __restrict__ beta,
                     float* __restrict__ out)
{
    int i = blockIdx.x * blockDim.x + threadIdx.x;
    if (i < NN) {
        out[i] = (z[i] - stats[0]) * stats[1] * gamma[0] + beta[0];
    }
}

// ---------------- launcher ------------------------------------------------------
extern "C" void kernel_launch(void* const* d_in, const int* in_sizes, int n_in,
                              void* d_out, int out_size)
{
    const float* feature = (const float*)d_in[0];
    const int*   ei      = (const int*)d_in[1];
    const float* head_W  = (const float*)d_in[2];
    const float* head_b  = (const float*)d_in[3];
    const float* gin_W1  = (const float*)d_in[4];
    const float* gin_b1  = (const float*)d_in[5];
    const float* lin_W1  = (const float*)d_in[6];
    const float* lin_b1  = (const float*)d_in[7];
    const float* gin_W2  = (const float*)d_in[8];
    const float* gin_b2  = (const float*)d_in[9];
    const float* lin_W2  = (const float*)d_in[10];
    const float* lin_b2  = (const float*)d_in[11];
    const float* tail_W  = (const float*)d_in[12];
    const float* tail_b  = (const float*)d_in[13];
    const float* bn_g    = (const float*)d_in[14];
    const float* bn_b    = (const float*)d_in[15];
    float* out = (float*)d_out;

    float *xp, *yp, *hp, *zp, *stp, *wfp, *bfp, *v2p, *zbp;
    int *degp, *rsp, *curp, *adjp;
    uint16_t *whip, *wlop;
    cudaGetSymbolAddress((void**)&xp,   g_x);
    cudaGetSymbolAddress((void**)&yp,   g_y);
    cudaGetSymbolAddress((void**)&hp,   g_h);
    cudaGetSymbolAddress((void**)&zp,   g_z);
    cudaGetSymbolAddress((void**)&stp,  g_stats);
    cudaGetSymbolAddress((void**)&degp, g_deg);
    cudaGetSymbolAddress((void**)&rsp,  g_rowstart);
    cudaGetSymbolAddress((void**)&curp, g_cursor);
    cudaGetSymbolAddress((void**)&adjp, g_adj);
    cudaGetSymbolAddress((void**)&wfp,  g_WF);
    cudaGetSymbolAddress((void**)&bfp,  g_bf);
    cudaGetSymbolAddress((void**)&v2p,  g_v2);
    cudaGetSymbolAddress((void**)&zbp,  g_zb);
    cudaGetSymbolAddress((void**)&whip, g_Whi);
    cudaGetSymbolAddress((void**)&wlop, g_Wlo);

    static bool attr_done = false;
    if (!attr_done) {
        cudaFuncSetAttribute(mma_gemm<true, 0>,  cudaFuncAttributeMaxDynamicSharedMemorySize, SMEM_GEMM);
        cudaFuncSetAttribute(mma_gemm<true, 1>,  cudaFuncAttributeMaxDynamicSharedMemorySize, SMEM_GEMM);
        attr_done = true;
    }

    const int gemmGrid = (NN + 63) / 64;
    const int edgeGrid = (EE + 255) / 256;
    const int nodeGrid = (NN + 255) / 256;
    const int warpGrid = (NN * 32 + 255) / 256;

    // ---- weight folds + conversions (tiny) ----
    fold_W_k<<<64, 256>>>(lin_W1, gin_W2, wfp);
    fold_b_k<<<1, 128>>>(lin_b1, gin_W2, bfp);
    fold_t_k<<<1, 128>>>(lin_W2, tail_W, lin_b2, tail_b, v2p, zbp);
    conv_w_k<<<(512 * 128 + 255) / 256, 256>>>(head_W, whip, wlop, 512, 0);
    conv_w_k<<<(128 * 128 + 255) / 256, 256>>>(gin_W1, whip, wlop, 128, 4);
    conv_w_k<<<(128 * 128 + 255) / 256, 256>>>(wfp,    whip, wlop, 128, 5);

    // ---- CSR build ----
    zero_deg_k<<<nodeGrid, 256>>>(degp);
    degree_k<<<edgeGrid, 256>>>(ei, degp);
    scan_k<<<1, 1024>>>(degp, rsp, curp);
    fill_k<<<edgeGrid, 256>>>(ei, curp, adjp);

    // head: x1 = relu(feature @ head_W + head_b)
    mma_gemm<true, 0><<<gemmGrid, 256, SMEM_GEMM>>>(
        feature, (const uint4*)whip, (const uint4*)wlop, head_b, nullptr, nullptr, xp, NN, 512, 0);

    // GIN layer 1: y1 = x1 + agg(x1); h1 = relu(y1 @ gin_W1 + gin_b1)
    gather_k<<<warpGrid, 256>>>(xp, rsp, adjp, yp);
    mma_gemm<true, 0><<<gemmGrid, 256, SMEM_GEMM>>>(
        yp, (const uint4*)whip, (const uint4*)wlop, gin_b1, nullptr, nullptr, hp, NN, 128, 4);

    // Layer 2 folded: y2 = h1 + agg(h1); h2 = relu(y2 @ WF + gin_b2 + (1+deg)*bf)
    gather_k<<<warpGrid, 256>>>(hp, rsp, adjp, xp);
    mma_gemm<true, 1><<<gemmGrid, 256, SMEM_GEMM>>>(
        xp, (const uint4*)whip, (const uint4*)wlop, gin_b2, bfp, rsp, yp, NN, 128, 5);

    // tail + BN
    tail_k<<<warpGrid, 256>>>(yp, v2p, zbp, zp);
    stats_k<<<1, 1024>>>(zp, stp);
    bn_k<<<nodeGrid, 256>>>(zp, stp, bn_g, bn_b, out);
}

// round 10
// speedup vs baseline: 2.3761x; 1.0858x over previous
#include <cuda_runtime.h>
#include <cuda_bf16.h>
#include <math.h>
#include <cstdint>

#define NN 50000
#define DH 128
#define EE 600000
#define NBLK 782            // ceil(NN/64)

// ---------------- scratch ------------------------------------------------------
__device__ float g_x[NN * DH];       // x1 (head out)
__device__ float g_h[NN * DH];       // h1
__device__ float g_z[NN];
__device__ float g_stats[2];
__device__ int   g_deg[NN];
__device__ int   g_rowstart[NN + 1];
__device__ int   g_cursor[NN];
__device__ int   g_adj[EE];
__device__ float g_WF[DH * DH];
__device__ float g_bf[DH];
__device__ float g_v2[DH];
__device__ float g_zb[1];
// Pre-converted weights: 6 chunks (head:0..3, gin_W1:4, WF:5), swizzled images.
__device__ uint16_t g_Whi[6 * 16384];
__device__ uint16_t g_Wlo[6 * 16384];
// Gather-output A images: per 64-row block, 64x128 bf16 swizzled (16KB each).
__device__ uint16_t g_Ahi[NBLK * 8192];
__device__ uint16_t g_Alo[NBLK * 8192];

// ---------------- helpers ------------------------------------------------------
__device__ __forceinline__ uint32_t smem_u32(const void* p) {
    uint32_t a;
    asm("{ .reg .u64 t; cvta.to.shared.u64 t, %1; cvt.u32.u64 %0, t; }" : "=r"(a) : "l"(p));
    return a;
}
__device__ __forceinline__ void ldsm_x4(uint32_t* r, uint32_t addr) {
    asm volatile("ldmatrix.sync.aligned.m8n8.x4.shared.b16 {%0,%1,%2,%3}, [%4];"
                 : "=r"(r[0]), "=r"(r[1]), "=r"(r[2]), "=r"(r[3]) : "r"(addr));
}
__device__ __forceinline__ void ldsm_x4_t(uint32_t* r, uint32_t addr) {
    asm volatile("ldmatrix.sync.aligned.m8n8.x4.trans.shared.b16 {%0,%1,%2,%3}, [%4];"
                 : "=r"(r[0]), "=r"(r[1]), "=r"(r[2]), "=r"(r[3]) : "r"(addr));
}
__device__ __forceinline__ void mma16816(float* d, const uint32_t* a, const uint32_t* b) {
    asm volatile(
        "mma.sync.aligned.m16n8k16.row.col.f32.bf16.bf16.f32 "
        "{%0,%1,%2,%3}, {%4,%5,%6,%7}, {%8,%9}, {%0,%1,%2,%3};"
        : "+f"(d[0]), "+f"(d[1]), "+f"(d[2]), "+f"(d[3])
        : "r"(a[0]), "r"(a[1]), "r"(a[2]), "r"(a[3]), "r"(b[0]), "r"(b[1]));
}
__device__ __forceinline__ uint32_t pack2(__nv_bfloat16 x, __nv_bfloat16 y) {
    __nv_bfloat162 t(x, y);
    return *(uint32_t*)&t;
}
__device__ __forceinline__ uint32_t sw_off(int row, int col) {
    return (uint32_t)row * 256u + (((uint32_t)col * 2u) ^ (((uint32_t)row & 7u) << 4));
}

static constexpr int OA_HI = 0;
static constexpr int OA_LO = 16384;
static constexpr int OB_HI = 32768;
static constexpr int OB_LO = 65536;
static constexpr int SMEM_GEMM = 98304;

// ---------------- weight pre-conversion ----------------------------------------
__global__ void conv_w_k(const float* __restrict__ W, uint16_t* __restrict__ Whi,
                         uint16_t* __restrict__ Wlo, int K, int chunkBase)
{
    int idx = blockIdx.x * blockDim.x + threadIdx.x;
    if (idx >= K * 128) return;
    int k = idx >> 7;
    int n = idx & 127;
    float v = W[idx];
    __nv_bfloat16 h = __float2bfloat16(v);
    __nv_bfloat16 l = __float2bfloat16(v - __bfloat162float(h));
    int c  = k >> 7;
    int kk = k & 127;
    uint32_t o = ((uint32_t)(chunkBase + c) * 32768u + sw_off(kk, n)) >> 1;
    Whi[o] = *(uint16_t*)&h;
    Wlo[o] = *(uint16_t*)&l;
}

// ---------------- HMMA GEMM -----------------------------------------------------
// FILL 0: A fp32 (cvt in-kernel, reg-prefetch). FILL 1: A pre-converted images.
// MODE 0: bias[col]. MODE 1: bias[col] + (1+deg_row)*bf[col].
// TAIL: fused dot with v2 -> z (no h store).
template <int FILL, int MODE, bool TAIL>
__global__ void __launch_bounds__(256, 2)
mma_gemm(const float* __restrict__ A,
         const uint4* __restrict__ Ahi, const uint4* __restrict__ Alo,
         const uint4* __restrict__ Whi, const uint4* __restrict__ Wlo,
         const float* __restrict__ bias, const float* __restrict__ bf,
         const int* __restrict__ rowstart,
         float* __restrict__ out,
         const float* __restrict__ v2, const float* __restrict__ zb,
         float* __restrict__ z,
         int M, int K, int chunkBase)
{
    extern __shared__ char smem[];
    const uint32_t sb = smem_u32(smem);
    const int tid  = threadIdx.x;
    const int wid  = tid >> 5;
    const int lane = tid & 31;
    const int wm = wid & 1;
    const int wn = wid >> 1;
    const int rowBase = blockIdx.x * 64;

    float acc[2][4][4];
#pragma unroll
    for (int i = 0; i < 2; i++)
#pragma unroll
        for (int j = 0; j < 4; j++)
#pragma unroll
            for (int q = 0; q < 4; q++) acc[i][j][q] = 0.f;

    const int grp = lane >> 3;
    const int li  = lane & 7;

    const int nchunk = (FILL == 0) ? (K >> 7) : 1;

    float4 pre[8];
    if (FILL == 0) {
#pragma unroll
        for (int t = 0; t < 8; t++) {
            int slot = tid + t * 256;
            int r  = slot >> 5;
            int k4 = (slot & 31) * 4;
            int grow = rowBase + r;
            pre[t] = make_float4(0.f, 0.f, 0.f, 0.f);
            if (grow < M)
                pre[t] = *(const float4*)&A[(size_t)grow * K + k4];
        }
    }

    for (int c = 0; c < nchunk; c++) {
        if (c > 0) __syncthreads();
        // ---- fill A
        if (FILL == 0) {
#pragma unroll
            for (int t = 0; t < 8; t++) {
                int slot = tid + t * 256;
                int r  = slot >> 5;
                int k4 = (slot & 31) * 4;
                float4 v = pre[t];
                __nv_bfloat16 h0 = __float2bfloat16(v.x), h1 = __float2bfloat16(v.y);
                __nv_bfloat16 h2 = __float2bfloat16(v.z), h3 = __float2bfloat16(v.w);
                float l0 = v.x - __bfloat162float(h0), l1 = v.y - __bfloat162float(h1);
                float l2 = v.z - __bfloat162float(h2), l3 = v.w - __bfloat162float(h3);
                uint32_t o = sw_off(r, k4);
                *(uint32_t*)(smem + OA_HI + o)     = pack2(h0, h1);
                *(uint32_t*)(smem + OA_HI + o + 4) = pack2(h2, h3);
                *(uint32_t*)(smem + OA_LO + o)     = pack2(__float2bfloat16(l0), __float2bfloat16(l1));
                *(uint32_t*)(smem + OA_LO + o + 4) = pack2(__float2bfloat16(l2), __float2bfloat16(l3));
            }
        } else {
            const uint4* aHi = Ahi + (size_t)blockIdx.x * 1024;
            const uint4* aLo = Alo + (size_t)blockIdx.x * 1024;
#pragma unroll
            for (int t = 0; t < 4; t++) {
                int slot = tid + t * 256;
                ((uint4*)(smem + OA_HI))[slot] = __ldg(&aHi[slot]);
                ((uint4*)(smem + OA_LO))[slot] = __ldg(&aLo[slot]);
            }
        }
        // ---- fill B (pre-swizzled images)
        const uint4* srcHi = Whi + (size_t)(chunkBase + c) * 2048;
        const uint4* srcLo = Wlo + (size_t)(chunkBase + c) * 2048;
#pragma unroll
        for (int t = 0; t < 8; t++) {
            int slot = tid + t * 256;
            ((uint4*)(smem + OB_HI))[slot] = __ldg(&srcHi[slot]);
            ((uint4*)(smem + OB_LO))[slot] = __ldg(&srcLo[slot]);
        }
        __syncthreads();

        // ---- prefetch next A chunk (overlaps compute)
        if (FILL == 0 && c + 1 < nchunk) {
#pragma unroll
            for (int t = 0; t < 8; t++) {
                int slot = tid + t * 256;
                int r  = slot >> 5;
                int k4 = (slot & 31) * 4;
                int grow = rowBase + r;
                pre[t] = make_float4(0.f, 0.f, 0.f, 0.f);
                if (grow < M)
                    pre[t] = *(const float4*)&A[(size_t)grow * K + (c + 1) * 128 + k4];
            }
        }

        // ---- 8 k-steps of 16
#pragma unroll
        for (int ks = 0; ks < 8; ks++) {
            int k0 = ks * 16;
            uint32_t ah[2][4], al[2][4];
#pragma unroll
            for (int mt = 0; mt < 2; mt++) {
                int r = wm * 32 + mt * 16 + li + (grp & 1) * 8;
                int kk = k0 + (grp >> 1) * 8;
                uint32_t addr = sb + OA_HI + sw_off(r, kk);
                ldsm_x4(ah[mt], addr);
                ldsm_x4(al[mt], addr + (OA_LO - OA_HI));
            }
            uint32_t bh[4][2], bl[4][2];
#pragma unroll
            for (int ntp = 0; ntp < 2; ntp++) {
                int kk = k0 + li + (grp & 1) * 8;
                int n  = wn * 32 + ntp * 16 + (grp >> 1) * 8;
                uint32_t addr = sb + OB_HI + sw_off(kk, n);
                uint32_t r4[4];
                ldsm_x4_t(r4, addr);
                bh[ntp * 2][0] = r4[0]; bh[ntp * 2][1] = r4[1];
                bh[ntp * 2 + 1][0] = r4[2]; bh[ntp * 2 + 1][1] = r4[3];
                ldsm_x4_t(r4, addr + (OB_LO - OB_HI));
                bl[ntp * 2][0] = r4[0]; bl[ntp * 2][1] = r4[1];
                bl[ntp * 2 + 1][0] = r4[2]; bl[ntp * 2 + 1][1] = r4[3];
            }
#pragma unroll
            for (int mt = 0; mt < 2; mt++)
#pragma unroll
                for (int nt = 0; nt < 4; nt++)
                    mma16816(acc[mt][nt], ah[mt], bh[nt]);
#pragma unroll
            for (int mt = 0; mt < 2; mt++)
#pragma unroll
                for (int nt = 0; nt < 4; nt++)
                    mma16816(acc[mt][nt], ah[mt], bl[nt]);
#pragma unroll
            for (int mt = 0; mt < 2; mt++)
#pragma unroll
                for (int nt = 0; nt < 4; nt++)
                    mma16816(acc[mt][nt], al[mt], bh[nt]);
        }
    }

    // ---- epilogue
    float p[2][2] = {{0.f, 0.f}, {0.f, 0.f}};   // TAIL partial dots [mt][half]
#pragma unroll
    for (int mt = 0; mt < 2; mt++) {
#pragma unroll
        for (int nt = 0; nt < 4; nt++) {
            int cc = wn * 32 + nt * 8 + (lane & 3) * 2;
            float b0 = __ldg(&bias[cc]);
            float b1 = __ldg(&bias[cc + 1]);
            float f0 = 0.f, f1 = 0.f;
            if (MODE == 1) { f0 = __ldg(&bf[cc]); f1 = __ldg(&bf[cc + 1]); }
            float w0 = 0.f, w1 = 0.f;
            if (TAIL) { w0 = __ldg(&v2[cc]); w1 = __ldg(&v2[cc + 1]); }
#pragma unroll
            for (int half = 0; half < 2; half++) {
                int row = rowBase + wm * 32 + mt * 16 + half * 8 + (lane >> 2);
                if (row < M) {
                    float v0 = acc[mt][nt][half * 2 + 0];
                    float v1 = acc[mt][nt][half * 2 + 1];
                    if (MODE == 1) {
                        float s = 1.f + (float)(__ldg(&rowstart[row + 1]) - __ldg(&rowstart[row]));
                        v0 += b0 + s * f0;
                        v1 += b1 + s * f1;
                    } else {
                        v0 += b0; v1 += b1;
                    }
                    v0 = fmaxf(v0, 0.f); v1 = fmaxf(v1, 0.f);
                    if (TAIL) {
                        p[mt][half] += v0 * w0 + v1 * w1;
                    } else {
                        *(float2*)&out[(size_t)row * 128 + cc] = make_float2(v0, v1);
                    }
                }
            }
        }
    }

    if (TAIL) {
        __syncthreads();                       // reuse smem for reduction
        float* red = (float*)(smem + OB_HI);   // [64][4]
#pragma unroll
        for (int mt = 0; mt < 2; mt++)
#pragma unroll
            for (int half = 0; half < 2; half++) {
                float s = p[mt][half];
                s += __shfl_xor_sync(0xFFFFFFFFu, s, 1);
                s += __shfl_xor_sync(0xFFFFFFFFu, s, 2);
                if ((lane & 3) == 0) {
                    int rl = wm * 32 + mt * 16 + half * 8 + (lane >> 2);
                    red[rl * 4 + wn] = s;
                }
            }
        __syncthreads();
        if (tid < 64) {
            int row = rowBase + tid;
            if (row < M) {
                float s = red[tid * 4 + 0] + red[tid * 4 + 1]
                        + red[tid * 4 + 2] + red[tid * 4 + 3];
                z[row] = s + zb[0];
            }
        }
    }
}

// ---------------- weight folding ------------------------------------------------
__global__ void fold_W_k(const float* __restrict__ L1, const float* __restrict__ G2,
                         float* __restrict__ WF)
{
    int idx = blockIdx.x * blockDim.x + threadIdx.x;
    int i = idx >> 7, j = idx & 127;
    float s = 0.f;
    for (int k = 0; k < 128; k++)
        s = fmaf(L1[i * 128 + k], G2[k * 128 + j], s);
    WF[idx] = s;
}
__global__ void fold_b_k(const float* __restrict__ bl1, const float* __restrict__ G2,
                         float* __restrict__ bf)
{
    int j = threadIdx.x;
    float s = 0.f;
    for (int i = 0; i < 128; i++)
        s = fmaf(bl1[i], G2[i * 128 + j], s);
    bf[j] = s;
}
__global__ void fold_t_k(const float* __restrict__ L2, const float* __restrict__ T,
                         const float* __restrict__ bl2, const float* __restrict__ bt,
                         float* __restrict__ v2, float* __restrict__ zb)
{
    int i = threadIdx.x;
    float s = 0.f;
    for (int k = 0; k < 128; k++)
        s = fmaf(L2[i * 128 + k], T[k], s);
    v2[i] = s;
    if (i == 0) {
        float z = bt[0];
        for (int k = 0; k < 128; k++) z = fmaf(bl2[k], T[k], z);
        zb[0] = z;
    }
}

// ---------------- CSR build ----------------------------------------------------
__global__ void zero_deg_k(int* __restrict__ deg)
{
    int i = blockIdx.x * blockDim.x + threadIdx.x;
    if (i < NN) deg[i] = 0;
}
__global__ void degree_k(const int* __restrict__ ei, int* __restrict__ deg)
{
    int e = blockIdx.x * blockDim.x + threadIdx.x;
    if (e < EE) atomicAdd(&deg[ei[EE + e]], 1);
}
__global__ void scan_k(const int* __restrict__ deg, int* __restrict__ rowstart,
                       int* __restrict__ cursor)
{
    __shared__ int sh[1024];
    const int tid = threadIdx.x;
    const int CH  = (NN + 1023) / 1024;
    const int base = tid * CH;

    int s = 0;
    for (int i = 0; i < CH; i++) {
        int idx = base + i;
        if (idx < NN) s += deg[idx];
    }
    sh[tid] = s;
    __syncthreads();
    for (int o = 1; o < 1024; o <<= 1) {
        int v = (tid >= o) ? sh[tid - o] : 0;
        __syncthreads();
        sh[tid] += v;
        __syncthreads();
    }
    int run = sh[tid] - s;
    for (int i = 0; i < CH; i++) {
        int idx = base + i;
        if (idx < NN) {
            rowstart[idx] = run;
            cursor[idx]   = run;
            run += deg[idx];
        }
    }
    if (tid == 1023) rowstart[NN] = sh[1023];
}
__global__ void fill_k(const int* __restrict__ ei, int* __restrict__ cursor,
                       int* __restrict__ adj)
{
    int e = blockIdx.x * blockDim.x + threadIdx.x;
    if (e < EE) {
        int s = ei[e];
        int d = ei[EE + e];
        int p = atomicAdd(&cursor[d], 1);
        adj[p] = s;
    }
}

// ---------------- gather -> bf16 hi/lo swizzled A-images ------------------------
__global__ void gather_img_k(const float* __restrict__ x,
                             const int* __restrict__ rowstart,
                             const int* __restrict__ adj,
                             uint16_t* __restrict__ imgHi,
                             uint16_t* __restrict__ imgLo)
{
    int idx = blockIdx.x * blockDim.x + threadIdx.x;
    int n = idx >> 5;
    if (n >= NN) return;
    int l = idx & 31;

    float4 acc = *(const float4*)&x[(size_t)n * 128 + l * 4];
    int start = __ldg(&rowstart[n]);
    int end   = __ldg(&rowstart[n + 1]);
    for (int j = start; j < end; j++) {
        int s = __ldg(&adj[j]);
        float4 v = *(const float4*)&x[(size_t)s * 128 + l * 4];
        acc.x += v.x; acc.y += v.y; acc.z += v.z; acc.w += v.w;
    }
    __nv_bfloat16 h0 = __float2bfloat16(acc.x), h1 = __float2bfloat16(acc.y);
    __nv_bfloat16 h2 = __float2bfloat16(acc.z), h3 = __float2bfloat16(acc.w);
    float l0 = acc.x - __bfloat162float(h0), l1 = acc.y - __bfloat162float(h1);
    float l2 = acc.z - __bfloat162float(h2), l3 = acc.w - __bfloat162float(h3);
    uint32_t o = (uint32_t)(n >> 6) * 16384u + sw_off(n & 63, l * 4);
    *(uint32_t*)((char*)imgHi + o)     = pack2(h0, h1);
    *(uint32_t*)((char*)imgHi + o + 4) = pack2(h2, h3);
    *(uint32_t*)((char*)imgLo + o)     = pack2(__float2bfloat16(l0), __float2bfloat16(l1));
    *(uint32_t*)((char*)imgLo + o + 4) = pack2(__float2bfloat16(l2), __float2bfloat16(l3));
}

// ---------------- BN -----------------------------------------------------------
__global__ void stats_k(const float* __restrict__ z, float* __restrict__ stats)
{
    __shared__ float sh[1024];
    int tid = threadIdx.x;

    float s = 0.f;
    for (int i = tid; i < NN; i += 1024) s += z[i];
    sh[tid] = s;
    __syncthreads();
    for (int o = 512; o > 0; o >>= 1) {
        if (tid < o) sh[tid] += sh[tid + o];
        __syncthreads();
    }
    float mu = sh[0] / (float)NN;
    __syncthreads();

    float v = 0.f;
    for (int i = tid; i < NN; i += 1024) {
        float d = z[i] - mu;
        v += d * d;
    }
    sh[tid] = v;
    __syncthreads();
    for (int o = 512; o > 0; o >>= 1) {
        if (tid < o) sh[tid] += sh[tid + o];
        __syncthreads();
    }
    if (tid == 0) {
        stats[0] = mu;
        stats[1] = rsqrtf(sh[0] / (float)NN + 1e-5f);
    }
}
__global__ void bn_k(const float* __restrict__ z, const float* __restrict__ stats,
                     const float* __restrict__ gamma, const float* __restrict__ beta,
                     float* __restrict__ out)
{
    int i = blockIdx.x * blockDim.x + threadIdx.x;
    if (i < NN) {
        out[i] = (z[i] - stats[0]) * stats[1] * gamma[0] + beta[0];
    }
}

// ---------------- launcher ------------------------------------------------------
extern "C" void kernel_launch(void* const* d_in, const int* in_sizes, int n_in,
                              void* d_out, int out_size)
{
    const float* feature = (const float*)d_in[0];
    const int*   ei      = (const int*)d_in[1];
    const float* head_W  = (const float*)d_in[2];
    const float* head_b  = (const float*)d_in[3];
    const float* gin_W1  = (const float*)d_in[4];
    const float* gin_b1  = (const float*)d_in[5];
    const float* lin_W1  = (const float*)d_in[6];
    const float* lin_b1  = (const float*)d_in[7];
    const float* gin_W2  = (const float*)d_in[8];
    const float* gin_b2  = (const float*)d_in[9];
    const float* lin_W2  = (const float*)d_in[10];
    const float* lin_b2  = (const float*)d_in[11];
    const float* tail_W  = (const float*)d_in[12];
    const float* tail_b  = (const float*)d_in[13];
    const float* bn_g    = (const float*)d_in[14];
    const float* bn_b    = (const float*)d_in[15];
    float* out = (float*)d_out;

    float *xp, *hp, *zp, *stp, *wfp, *bfp, *v2p, *zbp;
    int *degp, *rsp, *curp, *adjp;
    uint16_t *whip, *wlop, *ahip, *alop;
    cudaGetSymbolAddress((void**)&xp,   g_x);
    cudaGetSymbolAddress((void**)&hp,   g_h);
    cudaGetSymbolAddress((void**)&zp,   g_z);
    cudaGetSymbolAddress((void**)&stp,  g_stats);
    cudaGetSymbolAddress((void**)&degp, g_deg);
    cudaGetSymbolAddress((void**)&rsp,  g_rowstart);
    cudaGetSymbolAddress((void**)&curp, g_cursor);
    cudaGetSymbolAddress((void**)&adjp, g_adj);
    cudaGetSymbolAddress((void**)&wfp,  g_WF);
    cudaGetSymbolAddress((void**)&bfp,  g_bf);
    cudaGetSymbolAddress((void**)&v2p,  g_v2);
    cudaGetSymbolAddress((void**)&zbp,  g_zb);
    cudaGetSymbolAddress((void**)&whip, g_Whi);
    cudaGetSymbolAddress((void**)&wlop, g_Wlo);
    cudaGetSymbolAddress((void**)&ahip, g_Ahi);
    cudaGetSymbolAddress((void**)&alop, g_Alo);

    static cudaStream_t sA = nullptr, sB = nullptr;
    static cudaEvent_t e0, e1, e2;
    if (!sA) {
        cudaStreamCreateWithFlags(&sA, cudaStreamNonBlocking);
        cudaStreamCreateWithFlags(&sB, cudaStreamNonBlocking);
        cudaEventCreateWithFlags(&e0, cudaEventDisableTiming);
        cudaEventCreateWithFlags(&e1, cudaEventDisableTiming);
        cudaEventCreateWithFlags(&e2, cudaEventDisableTiming);
        cudaFuncSetAttribute(mma_gemm<0, 0, false>, cudaFuncAttributeMaxDynamicSharedMemorySize, SMEM_GEMM);
        cudaFuncSetAttribute(mma_gemm<1, 0, false>, cudaFuncAttributeMaxDynamicSharedMemorySize, SMEM_GEMM);
        cudaFuncSetAttribute(mma_gemm<1, 1, true>,  cudaFuncAttributeMaxDynamicSharedMemorySize, SMEM_GEMM);
    }

    const int gemmGrid = NBLK;
    const int edgeGrid = (EE + 255) / 256;
    const int nodeGrid = (NN + 255) / 256;
    const int warpGrid = (NN * 32 + 255) / 256;

    // ---- fork side work ----
    cudaEventRecord(e0, 0);

    // side A: CSR build
    cudaStreamWaitEvent(sA, e0, 0);
    zero_deg_k<<<nodeGrid, 256, 0, sA>>>(degp);
    degree_k<<<edgeGrid, 256, 0, sA>>>(ei, degp);
    scan_k<<<1, 1024, 0, sA>>>(degp, rsp, curp);
    fill_k<<<edgeGrid, 256, 0, sA>>>(ei, curp, adjp);
    cudaEventRecord(e1, sA);

    // side B: folds + layer-weight conversion
    cudaStreamWaitEvent(sB, e0, 0);
    fold_W_k<<<64, 256, 0, sB>>>(lin_W1, gin_W2, wfp);
    fold_b_k<<<1, 128, 0, sB>>>(lin_b1, gin_W2, bfp);
    fold_t_k<<<1, 128, 0, sB>>>(lin_W2, tail_W, lin_b2, tail_b, v2p, zbp);
    conv_w_k<<<(128 * 128 + 255) / 256, 256, 0, sB>>>(gin_W1, whip, wlop, 128, 4);
    conv_w_k<<<(128 * 128 + 255) / 256, 256, 0, sB>>>(wfp,    whip, wlop, 128, 5);
    cudaEventRecord(e2, sB);

    // main: head weight conversion + head GEMM
    conv_w_k<<<(512 * 128 + 255) / 256, 256>>>(head_W, whip, wlop, 512, 0);
    mma_gemm<0, 0, false><<<gemmGrid, 256, SMEM_GEMM>>>(
        feature, nullptr, nullptr, (const uint4*)whip, (const uint4*)wlop,
        head_b, nullptr, nullptr, xp, nullptr, nullptr, nullptr, NN, 512, 0);

    // join CSR; GIN layer 1
    cudaStreamWaitEvent(0, e1, 0);
    gather_img_k<<<warpGrid, 256>>>(xp, rsp, adjp, ahip, alop);
    cudaStreamWaitEvent(0, e2, 0);
    mma_gemm<1, 0, false><<<gemmGrid, 256, SMEM_GEMM>>>(
        nullptr, (const uint4*)ahip, (const uint4*)alop, (const uint4*)whip, (const uint4*)wlop,
        gin_b1, nullptr, nullptr, hp, nullptr, nullptr, nullptr, NN, 128, 4);

    // layer 2 (folded) + fused tail -> z
    gather_img_k<<<warpGrid, 256>>>(hp, rsp, adjp, ahip, alop);
    mma_gemm<1, 1, true><<<gemmGrid, 256, SMEM_GEMM>>>(
        nullptr, (const uint4*)ahip, (const uint4*)alop, (const uint4*)whip, (const uint4*)wlop,
        gin_b2, bfp, rsp, nullptr, v2p, zbp, zp, NN, 128, 5);

    // BN
    stats_k<<<1, 1024>>>(zp, stp);
    bn_k<<<nodeGrid, 256>>>(zp, stp, bn_g, bn_b, out);
}

// round 11
// speedup vs baseline: 2.9693x; 1.2497x over previous
#include <cuda_runtime.h>
#include <cuda_bf16.h>
#include <math.h>
#include <cstdint>

#define NN 50000
#define DH 128
#define EE 600000

// ---------------- scratch ------------------------------------------------------
__device__ float g_x[NN * DH];       // x1 (head out)
__device__ float g_h[NN * DH];       // h1
__device__ float g_z[NN];
__device__ float g_stats[2];
__device__ int   g_deg[NN];
__device__ int   g_rowstart[NN + 1];
__device__ int   g_cursor[NN];
__device__ int   g_adj[EE];
__device__ float g_WF[DH * DH];
__device__ float g_bf[DH];
__device__ float g_v2[DH];
__device__ float g_zb[1];
// Pre-converted weights: 6 chunks (head:0..3, gin_W1:4, WF:5), swizzled images.
__device__ uint16_t g_Whi[6 * 16384];
__device__ uint16_t g_Wlo[6 * 16384];

// ---------------- helpers ------------------------------------------------------
__device__ __forceinline__ uint32_t smem_u32(const void* p) {
    uint32_t a;
    asm("{ .reg .u64 t; cvta.to.shared.u64 t, %1; cvt.u32.u64 %0, t; }" : "=r"(a) : "l"(p));
    return a;
}
__device__ __forceinline__ void ldsm_x4(uint32_t* r, uint32_t addr) {
    asm volatile("ldmatrix.sync.aligned.m8n8.x4.shared.b16 {%0,%1,%2,%3}, [%4];"
                 : "=r"(r[0]), "=r"(r[1]), "=r"(r[2]), "=r"(r[3]) : "r"(addr));
}
__device__ __forceinline__ void ldsm_x4_t(uint32_t* r, uint32_t addr) {
    asm volatile("ldmatrix.sync.aligned.m8n8.x4.trans.shared.b16 {%0,%1,%2,%3}, [%4];"
                 : "=r"(r[0]), "=r"(r[1]), "=r"(r[2]), "=r"(r[3]) : "r"(addr));
}
__device__ __forceinline__ void mma16816(float* d, const uint32_t* a, const uint32_t* b) {
    asm volatile(
        "mma.sync.aligned.m16n8k16.row.col.f32.bf16.bf16.f32 "
        "{%0,%1,%2,%3}, {%4,%5,%6,%7}, {%8,%9}, {%0,%1,%2,%3};"
        : "+f"(d[0]), "+f"(d[1]), "+f"(d[2]), "+f"(d[3])
        : "r"(a[0]), "r"(a[1]), "r"(a[2]), "r"(a[3]), "r"(b[0]), "r"(b[1]));
}
__device__ __forceinline__ uint32_t pack2(__nv_bfloat16 x, __nv_bfloat16 y) {
    __nv_bfloat162 t(x, y);
    return *(uint32_t*)&t;
}
__device__ __forceinline__ uint32_t sw_off(int row, int col) {
    return (uint32_t)row * 256u + (((uint32_t)col * 2u) ^ (((uint32_t)row & 7u) << 4));
}

// layer GEMM smem (BM=64): A 16KB x2, B 32KB x2
static constexpr int OA_HI = 0;
static constexpr int OA_LO = 16384;
static constexpr int OB_HI = 32768;
static constexpr int OB_LO = 65536;
static constexpr int SMEM_LAYER = 98304;
// head GEMM smem (BM=128): A 32KB x2, B 32KB x2
static constexpr int HA_HI = 0;
static constexpr int HA_LO = 32768;
static constexpr int HB_HI = 65536;
static constexpr int HB_LO = 98304;
static constexpr int SMEM_HEAD = 131072;

// ---------------- weight pre-conversion ----------------------------------------
__global__ void conv_w_k(const float* __restrict__ W, uint16_t* __restrict__ Whi,
                         uint16_t* __restrict__ Wlo, int K, int chunkBase)
{
    int idx = blockIdx.x * blockDim.x + threadIdx.x;
    if (idx >= K * 128) return;
    int k = idx >> 7;
    int n = idx & 127;
    float v = W[idx];
    __nv_bfloat16 h = __float2bfloat16(v);
    __nv_bfloat16 l = __float2bfloat16(v - __bfloat162float(h));
    int c  = k >> 7;
    int kk = k & 127;
    uint32_t o = ((uint32_t)(chunkBase + c) * 32768u + sw_off(kk, n)) >> 1;
    Whi[o] = *(uint16_t*)&h;
    Wlo[o] = *(uint16_t*)&l;
}

// ---------------- head GEMM: BM=128, 512 threads, K=512 ------------------------
__global__ void __launch_bounds__(512, 1)
head_gemm(const float* __restrict__ A,
          const uint4* __restrict__ Whi, const uint4* __restrict__ Wlo,
          const float* __restrict__ bias, float* __restrict__ out)
{
    extern __shared__ char smem[];
    const uint32_t sb = smem_u32(smem);
    const int tid  = threadIdx.x;
    const int wid  = tid >> 5;
    const int lane = tid & 31;
    const int wm = wid & 3;          // 4 m-slabs of 32 rows
    const int wn = wid >> 2;         // 4 n-slabs of 32 cols
    const int rowBase = blockIdx.x * 128;
    const int M = NN, K = 512;

    float acc[2][4][4];
#pragma unroll
    for (int i = 0; i < 2; i++)
#pragma unroll
        for (int j = 0; j < 4; j++)
#pragma unroll
            for (int q = 0; q < 4; q++) acc[i][j][q] = 0.f;

    const int grp = lane >> 3;
    const int li  = lane & 7;

    float4 pre[8];
#pragma unroll
    for (int t = 0; t < 8; t++) {
        int slot = tid + t * 512;          // 0..4095
        int r  = slot >> 5;
        int k4 = (slot & 31) * 4;
        int grow = rowBase + r;
        pre[t] = make_float4(0.f, 0.f, 0.f, 0.f);
        if (grow < M)
            pre[t] = *(const float4*)&A[(size_t)grow * K + k4];
    }

    for (int c = 0; c < 4; c++) {
        if (c > 0) __syncthreads();
        // ---- fill A from prefetched regs
#pragma unroll
        for (int t = 0; t < 8; t++) {
            int slot = tid + t * 512;
            int r  = slot >> 5;
            int k4 = (slot & 31) * 4;
            float4 v = pre[t];
            __nv_bfloat16 h0 = __float2bfloat16(v.x), h1 = __float2bfloat16(v.y);
            __nv_bfloat16 h2 = __float2bfloat16(v.z), h3 = __float2bfloat16(v.w);
            float l0 = v.x - __bfloat162float(h0), l1 = v.y - __bfloat162float(h1);
            float l2 = v.z - __bfloat162float(h2), l3 = v.w - __bfloat162float(h3);
            uint32_t o = sw_off(r, k4);
            *(uint32_t*)(smem + HA_HI + o)     = pack2(h0, h1);
            *(uint32_t*)(smem + HA_HI + o + 4) = pack2(h2, h3);
            *(uint32_t*)(smem + HA_LO + o)     = pack2(__float2bfloat16(l0), __float2bfloat16(l1));
            *(uint32_t*)(smem + HA_LO + o + 4) = pack2(__float2bfloat16(l2), __float2bfloat16(l3));
        }
        // ---- fill B
        const uint4* srcHi = Whi + (size_t)c * 2048;
        const uint4* srcLo = Wlo + (size_t)c * 2048;
#pragma unroll
        for (int t = 0; t < 4; t++) {
            int slot = tid + t * 512;
            ((uint4*)(smem + HB_HI))[slot] = __ldg(&srcHi[slot]);
            ((uint4*)(smem + HB_LO))[slot] = __ldg(&srcLo[slot]);
        }
        __syncthreads();

        // ---- prefetch next chunk
        if (c < 3) {
#pragma unroll
            for (int t = 0; t < 8; t++) {
                int slot = tid + t * 512;
                int r  = slot >> 5;
                int k4 = (slot & 31) * 4;
                int grow = rowBase + r;
                pre[t] = make_float4(0.f, 0.f, 0.f, 0.f);
                if (grow < M)
                    pre[t] = *(const float4*)&A[(size_t)grow * K + (c + 1) * 128 + k4];
            }
        }

#pragma unroll
        for (int ks = 0; ks < 8; ks++) {
            int k0 = ks * 16;
            uint32_t ah[2][4], al[2][4];
#pragma unroll
            for (int mt = 0; mt < 2; mt++) {
                int r = wm * 32 + mt * 16 + li + (grp & 1) * 8;
                int kk = k0 + (grp >> 1) * 8;
                uint32_t addr = sb + HA_HI + sw_off(r, kk);
                ldsm_x4(ah[mt], addr);
                ldsm_x4(al[mt], addr + (HA_LO - HA_HI));
            }
            uint32_t bh[4][2], bl[4][2];
#pragma unroll
            for (int ntp = 0; ntp < 2; ntp++) {
                int kk = k0 + li + (grp & 1) * 8;
                int n  = wn * 32 + ntp * 16 + (grp >> 1) * 8;
                uint32_t addr = sb + HB_HI + sw_off(kk, n);
                uint32_t r4[4];
                ldsm_x4_t(r4, addr);
                bh[ntp * 2][0] = r4[0]; bh[ntp * 2][1] = r4[1];
                bh[ntp * 2 + 1][0] = r4[2]; bh[ntp * 2 + 1][1] = r4[3];
                ldsm_x4_t(r4, addr + (HB_LO - HB_HI));
                bl[ntp * 2][0] = r4[0]; bl[ntp * 2][1] = r4[1];
                bl[ntp * 2 + 1][0] = r4[2]; bl[ntp * 2 + 1][1] = r4[3];
            }
#pragma unroll
            for (int mt = 0; mt < 2; mt++)
#pragma unroll
                for (int nt = 0; nt < 4; nt++)
                    mma16816(acc[mt][nt], ah[mt], bh[nt]);
#pragma unroll
            for (int mt = 0; mt < 2; mt++)
#pragma unroll
                for (int nt = 0; nt < 4; nt++)
                    mma16816(acc[mt][nt], ah[mt], bl[nt]);
#pragma unroll
            for (int mt = 0; mt < 2; mt++)
#pragma unroll
                for (int nt = 0; nt < 4; nt++)
                    mma16816(acc[mt][nt], al[mt], bh[nt]);
        }
    }

#pragma unroll
    for (int mt = 0; mt < 2; mt++) {
#pragma unroll
        for (int nt = 0; nt < 4; nt++) {
            int cc = wn * 32 + nt * 8 + (lane & 3) * 2;
            float b0 = __ldg(&bias[cc]);
            float b1 = __ldg(&bias[cc + 1]);
#pragma unroll
            for (int half = 0; half < 2; half++) {
                int row = rowBase + wm * 32 + mt * 16 + half * 8 + (lane >> 2);
                if (row < M) {
                    float v0 = fmaxf(acc[mt][nt][half * 2 + 0] + b0, 0.f);
                    float v1 = fmaxf(acc[mt][nt][half * 2 + 1] + b1, 0.f);
                    *(float2*)&out[(size_t)row * 128 + cc] = make_float2(v0, v1);
                }
            }
        }
    }
}

// ---------------- layer GEMM with fused gather ----------------------------------
// A = gather(x): y[n] = x[n] + sum_{s in N(n)} x[s], built in smem (bf16 hi/lo).
// MODE 0: bias[col]. MODE 1: bias[col] + (1+deg_row)*bf[col].
// TAIL: fused dot with v2 -> z.
template <int MODE, bool TAIL>
__global__ void __launch_bounds__(256, 2)
layer_gemm(const float* __restrict__ x,
           const int* __restrict__ rowstart, const int* __restrict__ adj,
           const uint4* __restrict__ Whi, const uint4* __restrict__ Wlo,
           const float* __restrict__ bias, const float* __restrict__ bf,
           float* __restrict__ out,
           const float* __restrict__ v2, const float* __restrict__ zb,
           float* __restrict__ z, int chunkBase)
{
    extern __shared__ char smem[];
    const uint32_t sb = smem_u32(smem);
    const int tid  = threadIdx.x;
    const int wid  = tid >> 5;
    const int lane = tid & 31;
    const int wm = wid & 1;
    const int wn = wid >> 1;
    const int rowBase = blockIdx.x * 64;
    const int M = NN;

    // ---- fused gather fill: warp w owns rows w*8 .. w*8+7
#pragma unroll
    for (int rr = 0; rr < 8; rr++) {
        int r = wid * 8 + rr;
        int n = rowBase + r;
        float4 acc = make_float4(0.f, 0.f, 0.f, 0.f);
        if (n < M) {
            acc = *(const float4*)&x[(size_t)n * 128 + lane * 4];
            int start = __ldg(&rowstart[n]);
            int end   = __ldg(&rowstart[n + 1]);
            for (int j = start; j < end; j++) {
                int s = __ldg(&adj[j]);
                float4 v = *(const float4*)&x[(size_t)s * 128 + lane * 4];
                acc.x += v.x; acc.y += v.y; acc.z += v.z; acc.w += v.w;
            }
        }
        __nv_bfloat16 h0 = __float2bfloat16(acc.x), h1 = __float2bfloat16(acc.y);
        __nv_bfloat16 h2 = __float2bfloat16(acc.z), h3 = __float2bfloat16(acc.w);
        float l0 = acc.x - __bfloat162float(h0), l1 = acc.y - __bfloat162float(h1);
        float l2 = acc.z - __bfloat162float(h2), l3 = acc.w - __bfloat162float(h3);
        uint32_t o = sw_off(r, lane * 4);
        *(uint32_t*)(smem + OA_HI + o)     = pack2(h0, h1);
        *(uint32_t*)(smem + OA_HI + o + 4) = pack2(h2, h3);
        *(uint32_t*)(smem + OA_LO + o)     = pack2(__float2bfloat16(l0), __float2bfloat16(l1));
        *(uint32_t*)(smem + OA_LO + o + 4) = pack2(__float2bfloat16(l2), __float2bfloat16(l3));
    }
    // ---- fill B
    const uint4* srcHi = Whi + (size_t)chunkBase * 2048;
    const uint4* srcLo = Wlo + (size_t)chunkBase * 2048;
#pragma unroll
    for (int t = 0; t < 8; t++) {
        int slot = tid + t * 256;
        ((uint4*)(smem + OB_HI))[slot] = __ldg(&srcHi[slot]);
        ((uint4*)(smem + OB_LO))[slot] = __ldg(&srcLo[slot]);
    }
    __syncthreads();

    float acc[2][4][4];
#pragma unroll
    for (int i = 0; i < 2; i++)
#pragma unroll
        for (int j = 0; j < 4; j++)
#pragma unroll
            for (int q = 0; q < 4; q++) acc[i][j][q] = 0.f;

    const int grp = lane >> 3;
    const int li  = lane & 7;

#pragma unroll
    for (int ks = 0; ks < 8; ks++) {
        int k0 = ks * 16;
        uint32_t ah[2][4], al[2][4];
#pragma unroll
        for (int mt = 0; mt < 2; mt++) {
            int r = wm * 32 + mt * 16 + li + (grp & 1) * 8;
            int kk = k0 + (grp >> 1) * 8;
            uint32_t addr = sb + OA_HI + sw_off(r, kk);
            ldsm_x4(ah[mt], addr);
            ldsm_x4(al[mt], addr + (OA_LO - OA_HI));
        }
        uint32_t bh[4][2], bl[4][2];
#pragma unroll
        for (int ntp = 0; ntp < 2; ntp++) {
            int kk = k0 + li + (grp & 1) * 8;
            int n  = wn * 32 + ntp * 16 + (grp >> 1) * 8;
            uint32_t addr = sb + OB_HI + sw_off(kk, n);
            uint32_t r4[4];
            ldsm_x4_t(r4, addr);
            bh[ntp * 2][0] = r4[0]; bh[ntp * 2][1] = r4[1];
            bh[ntp * 2 + 1][0] = r4[2]; bh[ntp * 2 + 1][1] = r4[3];
            ldsm_x4_t(r4, addr + (OB_LO - OB_HI));
            bl[ntp * 2][0] = r4[0]; bl[ntp * 2][1] = r4[1];
            bl[ntp * 2 + 1][0] = r4[2]; bl[ntp * 2 + 1][1] = r4[3];
        }
#pragma unroll
        for (int mt = 0; mt < 2; mt++)
#pragma unroll
            for (int nt = 0; nt < 4; nt++)
                mma16816(acc[mt][nt], ah[mt], bh[nt]);
#pragma unroll
        for (int mt = 0; mt < 2; mt++)
#pragma unroll
            for (int nt = 0; nt < 4; nt++)
                mma16816(acc[mt][nt], ah[mt], bl[nt]);
#pragma unroll
        for (int mt = 0; mt < 2; mt++)
#pragma unroll
            for (int nt = 0; nt < 4; nt++)
                mma16816(acc[mt][nt], al[mt], bh[nt]);
    }

    // ---- epilogue
    float p[2][2] = {{0.f, 0.f}, {0.f, 0.f}};
#pragma unroll
    for (int mt = 0; mt < 2; mt++) {
#pragma unroll
        for (int nt = 0; nt < 4; nt++) {
            int cc = wn * 32 + nt * 8 + (lane & 3) * 2;
            float b0 = __ldg(&bias[cc]);
            float b1 = __ldg(&bias[cc + 1]);
            float f0 = 0.f, f1 = 0.f;
            if (MODE == 1) { f0 = __ldg(&bf[cc]); f1 = __ldg(&bf[cc + 1]); }
            float w0 = 0.f, w1 = 0.f;
            if (TAIL) { w0 = __ldg(&v2[cc]); w1 = __ldg(&v2[cc + 1]); }
#pragma unroll
            for (int half = 0; half < 2; half++) {
                int row = rowBase + wm * 32 + mt * 16 + half * 8 + (lane >> 2);
                if (row < M) {
                    float v0 = acc[mt][nt][half * 2 + 0];
                    float v1 = acc[mt][nt][half * 2 + 1];
                    if (MODE == 1) {
                        float s = 1.f + (float)(__ldg(&rowstart[row + 1]) - __ldg(&rowstart[row]));
                        v0 += b0 + s * f0;
                        v1 += b1 + s * f1;
                    } else {
                        v0 += b0; v1 += b1;
                    }
                    v0 = fmaxf(v0, 0.f); v1 = fmaxf(v1, 0.f);
                    if (TAIL) {
                        p[mt][half] += v0 * w0 + v1 * w1;
                    } else {
                        *(float2*)&out[(size_t)row * 128 + cc] = make_float2(v0, v1);
                    }
                }
            }
        }
    }

    if (TAIL) {
        __syncthreads();
        float* red = (float*)(smem + OB_HI);   // [64][4]
#pragma unroll
        for (int mt = 0; mt < 2; mt++)
#pragma unroll
            for (int half = 0; half < 2; half++) {
                float s = p[mt][half];
                s += __shfl_xor_sync(0xFFFFFFFFu, s, 1);
                s += __shfl_xor_sync(0xFFFFFFFFu, s, 2);
                if ((lane & 3) == 0) {
                    int rl = wm * 32 + mt * 16 + half * 8 + (lane >> 2);
                    red[rl * 4 + wn] = s;
                }
            }
        __syncthreads();
        if (tid < 64) {
            int row = rowBase + tid;
            if (row < M) {
                float s = red[tid * 4 + 0] + red[tid * 4 + 1]
                        + red[tid * 4 + 2] + red[tid * 4 + 3];
                z[row] = s + zb[0];
            }
        }
    }
}

// ---------------- weight folding ------------------------------------------------
__global__ void fold_W_k(const float* __restrict__ L1, const float* __restrict__ G2,
                         float* __restrict__ WF)
{
    int idx = blockIdx.x * blockDim.x + threadIdx.x;
    int i = idx >> 7, j = idx & 127;
    float s = 0.f;
    for (int k = 0; k < 128; k++)
        s = fmaf(L1[i * 128 + k], G2[k * 128 + j], s);
    WF[idx] = s;
}
__global__ void fold_b_k(const float* __restrict__ bl1, const float* __restrict__ G2,
                         float* __restrict__ bf)
{
    int j = threadIdx.x;
    float s = 0.f;
    for (int i = 0; i < 128; i++)
        s = fmaf(bl1[i], G2[i * 128 + j], s);
    bf[j] = s;
}
__global__ void fold_t_k(const float* __restrict__ L2, const float* __restrict__ T,
                         const float* __restrict__ bl2, const float* __restrict__ bt,
                         float* __restrict__ v2, float* __restrict__ zb)
{
    int i = threadIdx.x;
    float s = 0.f;
    for (int k = 0; k < 128; k++)
        s = fmaf(L2[i * 128 + k], T[k], s);
    v2[i] = s;
    if (i == 0) {
        float z = bt[0];
        for (int k = 0; k < 128; k++) z = fmaf(bl2[k], T[k], z);
        zb[0] = z;
    }
}

// ---------------- CSR build ----------------------------------------------------
__global__ void zero_deg_k(int* __restrict__ deg)
{
    int i = blockIdx.x * blockDim.x + threadIdx.x;
    if (i < NN) deg[i] = 0;
}
__global__ void degree_k(const int* __restrict__ ei, int* __restrict__ deg)
{
    int e = blockIdx.x * blockDim.x + threadIdx.x;
    if (e < EE) atomicAdd(&deg[ei[EE + e]], 1);
}
__global__ void scan_k(const int* __restrict__ deg, int* __restrict__ rowstart,
                       int* __restrict__ cursor)
{
    __shared__ int sh[1024];
    const int tid = threadIdx.x;
    const int CH  = (NN + 1023) / 1024;
    const int base = tid * CH;

    int s = 0;
    for (int i = 0; i < CH; i++) {
        int idx = base + i;
        if (idx < NN) s += deg[idx];
    }
    sh[tid] = s;
    __syncthreads();
    for (int o = 1; o < 1024; o <<= 1) {
        int v = (tid >= o) ? sh[tid - o] : 0;
        __syncthreads();
        sh[tid] += v;
        __syncthreads();
    }
    int run = sh[tid] - s;
    for (int i = 0; i < CH; i++) {
        int idx = base + i;
        if (idx < NN) {
            rowstart[idx] = run;
            cursor[idx]   = run;
            run += deg[idx];
        }
    }
    if (tid == 1023) rowstart[NN] = sh[1023];
}
__global__ void fill_k(const int* __restrict__ ei, int* __restrict__ cursor,
                       int* __restrict__ adj)
{
    int e = blockIdx.x * blockDim.x + threadIdx.x;
    if (e < EE) {
        int s = ei[e];
        int d = ei[EE + e];
        int p = atomicAdd(&cursor[d], 1);
        adj[p] = s;
    }
}

// ---------------- BN -----------------------------------------------------------
__global__ void stats_k(const float* __restrict__ z, float* __restrict__ stats)
{
    __shared__ float sh[1024];
    int tid = threadIdx.x;

    float s = 0.f;
    for (int i = tid; i < NN; i += 1024) s += z[i];
    sh[tid] = s;
    __syncthreads();
    for (int o = 512; o > 0; o >>= 1) {
        if (tid < o) sh[tid] += sh[tid + o];
        __syncthreads();
    }
    float mu = sh[0] / (float)NN;
    __syncthreads();

    float v = 0.f;
    for (int i = tid; i < NN; i += 1024) {
        float d = z[i] - mu;
        v += d * d;
    }
    sh[tid] = v;
    __syncthreads();
    for (int o = 512; o > 0; o >>= 1) {
        if (tid < o) sh[tid] += sh[tid + o];
        __syncthreads();
    }
    if (tid == 0) {
        stats[0] = mu;
        stats[1] = rsqrtf(sh[0] / (float)NN + 1e-5f);
    }
}
__global__ void bn_k(const float* __restrict__ z, const float* __restrict__ stats,
                     const float* __restrict__ gamma, const float* __restrict__ beta,
                     float* __restrict__ out)
{
    int i = blockIdx.x * blockDim.x + threadIdx.x;
    if (i < NN) {
        out[i] = (z[i] - stats[0]) * stats[1] * gamma[0] + beta[0];
    }
}

// ---------------- launcher ------------------------------------------------------
extern "C" void kernel_launch(void* const* d_in, const int* in_sizes, int n_in,
                              void* d_out, int out_size)
{
    const float* feature = (const float*)d_in[0];
    const int*   ei      = (const int*)d_in[1];
    const float* head_W  = (const float*)d_in[2];
    const float* head_b  = (const float*)d_in[3];
    const float* gin_W1  = (const float*)d_in[4];
    const float* gin_b1  = (const float*)d_in[5];
    const float* lin_W1  = (const float*)d_in[6];
    const float* lin_b1  = (const float*)d_in[7];
    const float* gin_W2  = (const float*)d_in[8];
    const float* gin_b2  = (const float*)d_in[9];
    const float* lin_W2  = (const float*)d_in[10];
    const float* lin_b2  = (const float*)d_in[11];
    const float* tail_W  = (const float*)d_in[12];
    const float* tail_b  = (const float*)d_in[13];
    const float* bn_g    = (const float*)d_in[14];
    const float* bn_b    = (const float*)d_in[15];
    float* out = (float*)d_out;

    float *xp, *hp, *zp, *stp, *wfp, *bfp, *v2p, *zbp;
    int *degp, *rsp, *curp, *adjp;
    uint16_t *whip, *wlop;
    cudaGetSymbolAddress((void**)&xp,   g_x);
    cudaGetSymbolAddress((void**)&hp,   g_h);
    cudaGetSymbolAddress((void**)&zp,   g_z);
    cudaGetSymbolAddress((void**)&stp,  g_stats);
    cudaGetSymbolAddress((void**)&degp, g_deg);
    cudaGetSymbolAddress((void**)&rsp,  g_rowstart);
    cudaGetSymbolAddress((void**)&curp, g_cursor);
    cudaGetSymbolAddress((void**)&adjp, g_adj);
    cudaGetSymbolAddress((void**)&wfp,  g_WF);
    cudaGetSymbolAddress((void**)&bfp,  g_bf);
    cudaGetSymbolAddress((void**)&v2p,  g_v2);
    cudaGetSymbolAddress((void**)&zbp,  g_zb);
    cudaGetSymbolAddress((void**)&whip, g_Whi);
    cudaGetSymbolAddress((void**)&wlop, g_Wlo);

    static cudaStream_t sA = nullptr, sB = nullptr;
    static cudaEvent_t e0, e1, e2;
    if (!sA) {
        cudaStreamCreateWithFlags(&sA, cudaStreamNonBlocking);
        cudaStreamCreateWithFlags(&sB, cudaStreamNonBlocking);
        cudaEventCreateWithFlags(&e0, cudaEventDisableTiming);
        cudaEventCreateWithFlags(&e1, cudaEventDisableTiming);
        cudaEventCreateWithFlags(&e2, cudaEventDisableTiming);
        cudaFuncSetAttribute(head_gemm, cudaFuncAttributeMaxDynamicSharedMemorySize, SMEM_HEAD);
        cudaFuncSetAttribute(layer_gemm<0, false>, cudaFuncAttributeMaxDynamicSharedMemorySize, SMEM_LAYER);
        cudaFuncSetAttribute(layer_gemm<1, true>,  cudaFuncAttributeMaxDynamicSharedMemorySize, SMEM_LAYER);
    }

    const int headGrid  = (NN + 127) / 128;   // 391
    const int layerGrid = (NN + 63) / 64;     // 782
    const int edgeGrid  = (EE + 255) / 256;
    const int nodeGrid  = (NN + 255) / 256;

    // ---- fork side work ----
    cudaEventRecord(e0, 0);

    // side A: CSR build
    cudaStreamWaitEvent(sA, e0, 0);
    zero_deg_k<<<nodeGrid, 256, 0, sA>>>(degp);
    degree_k<<<edgeGrid, 256, 0, sA>>>(ei, degp);
    scan_k<<<1, 1024, 0, sA>>>(degp, rsp, curp);
    fill_k<<<edgeGrid, 256, 0, sA>>>(ei, curp, adjp);
    cudaEventRecord(e1, sA);

    // side B: folds + layer-weight conversion
    cudaStreamWaitEvent(sB, e0, 0);
    fold_W_k<<<64, 256, 0, sB>>>(lin_W1, gin_W2, wfp);
    fold_b_k<<<1, 128, 0, sB>>>(lin_b1, gin_W2, bfp);
    fold_t_k<<<1, 128, 0, sB>>>(lin_W2, tail_W, lin_b2, tail_b, v2p, zbp);
    conv_w_k<<<(128 * 128 + 255) / 256, 256, 0, sB>>>(gin_W1, whip, wlop, 128, 4);
    conv_w_k<<<(128 * 128 + 255) / 256, 256, 0, sB>>>(wfp,    whip, wlop, 128, 5);
    cudaEventRecord(e2, sB);

    // main: head weight conversion + head GEMM
    conv_w_k<<<(512 * 128 + 255) / 256, 256>>>(head_W, whip, wlop, 512, 0);
    head_gemm<<<headGrid, 512, SMEM_HEAD>>>(
        feature, (const uint4*)whip, (const uint4*)wlop, head_b, xp);

    // join; GIN layer 1 (fused gather + GEMM): h1 = relu(gather(x1) @ W1 + b1)
    cudaStreamWaitEvent(0, e1, 0);
    cudaStreamWaitEvent(0, e2, 0);
    layer_gemm<0, false><<<layerGrid, 256, SMEM_LAYER>>>(
        xp, rsp, adjp, (const uint4*)whip, (const uint4*)wlop,
        gin_b1, nullptr, hp, nullptr, nullptr, nullptr, 4);

    // layer 2 (folded) + fused tail -> z
    layer_gemm<1, true><<<layerGrid, 256, SMEM_LAYER>>>(
        hp, rsp, adjp, (const uint4*)whip, (const uint4*)wlop,
        gin_b2, bfp, nullptr, v2p, zbp, zp, 5);

    // BN
    stats_k<<<1, 1024>>>(zp, stp);
    bn_k<<<nodeGrid, 256>>>(zp, stp, bn_g, bn_b, out);
}